// round 11
// baseline (speedup 1.0000x reference)
#include <cuda_runtime.h>
#include <cuda_fp16.h>
#include <cstdint>
#include <cstddef>

// out = relu(x[131072,256] @ W[256,256]^T + b[256]), fp32 in/out.
// Persistent-CTA fp16 mma.m16n8k16: 148 CTAs (1/SM) x 512 threads, warp tile
// 32x64. ALL of W (fp16, 256x256, 135KB, stride 528B) resident in smem for the
// whole kernel -> steady-state mainloop has no B loads/waits. Per 128-row tile:
// A staged via LDG+cvt+STS 2-buffer ring; 4 barriers; epilogue overlapped by
// next tile's prefetched A.

#define DEVI __device__ __forceinline__

static constexpr int M_TOTAL = 131072;
static constexpr int N = 256;
static constexpr int K = 256;
static constexpr int BM = 128;                    // M rows per tile
static constexpr int KC = 64;                     // K per A chunk
static constexpr int NCTA = 148;
static constexpr int STRB_A = 144;                // A row stride bytes
static constexpr int STRB_B = 528;                // B row stride bytes (256h+8h)
static constexpr int A_STAGE = BM * STRB_A;       // 18432
static constexpr int A_BASE = 1024;               // [0,1024) bias
static constexpr int B_BASE = A_BASE + 2 * A_STAGE;        // 37888
static constexpr int SMEM_TOTAL = B_BASE + N * STRB_B;     // 173056

__device__ __half g_wh[N * K];

DEVI uint32_t smem_u32(const void* p) {
    uint32_t a;
    asm("{ .reg .u64 t; cvta.to.shared.u64 t, %1; cvt.u32.u64 %0, t; }"
        : "=r"(a) : "l"(p));
    return a;
}

DEVI void cp16(uint32_t dst, const void* src) {
    asm volatile("cp.async.cg.shared.global [%0], [%1], 16;"
                 :: "r"(dst), "l"(__cvta_generic_to_global(src)) : "memory");
}

DEVI uint32_t pack_h2(float lo, float hi) {
    uint32_t r;
    asm("cvt.rn.f16x2.f32 %0, %1, %2;" : "=r"(r) : "f"(hi), "f"(lo));
    return r;
}

DEVI void ldm_x4(uint32_t* r, uint32_t addr) {
    asm volatile("ldmatrix.sync.aligned.m8n8.x4.shared.b16 {%0,%1,%2,%3}, [%4];"
                 : "=r"(r[0]), "=r"(r[1]), "=r"(r[2]), "=r"(r[3]) : "r"(addr));
}

DEVI void mma_f16(float* c, const uint32_t* a, const uint32_t* b) {
    asm volatile(
        "mma.sync.aligned.m16n8k16.row.col.f32.f16.f16.f32 "
        "{%0,%1,%2,%3}, {%4,%5,%6,%7}, {%8,%9}, {%0,%1,%2,%3};"
        : "+f"(c[0]), "+f"(c[1]), "+f"(c[2]), "+f"(c[3])
        : "r"(a[0]), "r"(a[1]), "r"(a[2]), "r"(a[3]), "r"(b[0]), "r"(b[1]));
}

__global__ void convert_w_kernel(const float* __restrict__ W) {
    int idx4 = (blockIdx.x * 256 + threadIdx.x) * 4;
    float4 v = *reinterpret_cast<const float4*>(W + idx4);
    uint2 h;
    h.x = pack_h2(v.x, v.y);
    h.y = pack_h2(v.z, v.w);
    *reinterpret_cast<uint2*>(g_wh + idx4) = h;
}

__global__ void __launch_bounds__(512, 1)
gemm_f16_kernel(const float* __restrict__ x,
                const float* __restrict__ bias,
                float* __restrict__ out) {
    extern __shared__ char smem[];
    float* sbias = reinterpret_cast<float*>(smem);
    const uint32_t sbase = smem_u32(smem);
    const int tid  = threadIdx.x;
    const int lane = tid & 31;
    const int wid  = tid >> 5;
    const int warp_m = wid >> 2;       // 0..3 (32 M rows each)
    const int warp_n = wid & 3;        // 0..3 (64 N cols each)
    const int gid = lane >> 2;
    const int tg  = lane & 3;

    if (tid < N) sbias[tid] = bias[tid];

    const uint32_t aOff = (uint32_t)((warp_m * 32 + (lane & 15)) * STRB_A
                                     + (lane >> 4) * 16);
    const uint32_t bOff = (uint32_t)((warp_n * 64 + (lane & 7) + ((lane >> 4) << 3)) * STRB_B
                                     + ((lane >> 3) & 1) * 16);

    float acc[2][8][4];
    #pragma unroll
    for (int mt = 0; mt < 2; ++mt)
        #pragma unroll
        for (int nt = 0; nt < 8; ++nt)
            #pragma unroll
            for (int j = 0; j < 4; ++j)
                acc[mt][nt][j] = 0.0f;

    // A loader: 128 rows x 16 8B-granules = 2048 granules, 4 per thread
    const int ar = tid >> 4;           // row 0..31 (+32 per i)
    const int ac = tid & 15;

    auto ldg_A = [&](int m_base, int kt, float4* pf) {
        const float* srcA = x + (size_t)m_base * K + kt * KC;
        #pragma unroll
        for (int i = 0; i < 4; ++i)
            pf[i] = *reinterpret_cast<const float4*>(srcA + (size_t)(ar + i * 32) * K + ac * 4);
    };
    auto sts_A = [&](int buf, const float4* pf) {
        char* dA = smem + A_BASE + buf * A_STAGE;
        #pragma unroll
        for (int i = 0; i < 4; ++i) {
            uint2 h;
            h.x = pack_h2(pf[i].x, pf[i].y);
            h.y = pack_h2(pf[i].z, pf[i].w);
            *reinterpret_cast<uint2*>(dA + (ar + i * 32) * STRB_A + ac * 8) = h;
        }
    };

    // ---- One-time prologue: W resident in smem + first A chunk ----
    {
        // B: 256 rows x 32 16B-granules = 8192 granules, 16 per thread
        #pragma unroll
        for (int i = 0; i < 16; ++i) {
            int g = tid + i * 512;
            int r = g >> 5, c = g & 31;
            cp16(sbase + B_BASE + r * STRB_B + c * 16, g_wh + (size_t)r * K + c * 8);
        }
        asm volatile("cp.async.commit_group;" ::: "memory");

        float4 pf[4];
        ldg_A(blockIdx.x * BM, 0, pf);
        sts_A(0, pf);
        asm volatile("cp.async.wait_group 0;" ::: "memory");
        __syncthreads();    // B + A(chunk0) visible everywhere
    }

    // ---- Persistent tile loop ----
    const int m_stride = NCTA * BM;
    #pragma unroll 1
    for (int m_base = blockIdx.x * BM; m_base < M_TOTAL; m_base += m_stride) {
        #pragma unroll
        for (int kt = 0; kt < 4; ++kt) {
            if (kt > 0) __syncthreads();     // A(kt) visible (kt=0 synced before)

            // next chunk: (m, kt+1) or (m+stride, 0)
            const int nm = (kt < 3) ? m_base : m_base + m_stride;
            const int nk = (kt < 3) ? kt + 1 : 0;
            const bool has_next = (nm < M_TOTAL);
            float4 pf[4];
            if (has_next) ldg_A(nm, nk, pf);     // LDG rides over the MMA block

            const uint32_t aBase = sbase + A_BASE + (kt & 1) * A_STAGE + aOff;
            const uint32_t bBase = sbase + B_BASE + kt * (KC * 2) + bOff;

            uint32_t a[2][2][4], b[2][4][4];
            ldm_x4(a[0][0], aBase);
            ldm_x4(a[0][1], aBase + 16 * STRB_A);
            #pragma unroll
            for (int j = 0; j < 4; ++j)
                ldm_x4(b[0][j], bBase + (16 * j) * STRB_B);

            #pragma unroll
            for (int ks = 0; ks < 4; ++ks) {
                const int cur = ks & 1, nxt = cur ^ 1;
                if (ks < 3) {
                    ldm_x4(a[nxt][0], aBase + (ks + 1) * 32);
                    ldm_x4(a[nxt][1], aBase + 16 * STRB_A + (ks + 1) * 32);
                    #pragma unroll
                    for (int j = 0; j < 4; ++j)
                        ldm_x4(b[nxt][j], bBase + (16 * j) * STRB_B + (ks + 1) * 32);
                }
                #pragma unroll
                for (int mt = 0; mt < 2; ++mt)
                    #pragma unroll
                    for (int nt = 0; nt < 8; ++nt)
                        mma_f16(acc[mt][nt], a[cur][mt], &b[cur][nt >> 1][(nt & 1) * 2]);
            }

            if (has_next) sts_A(nk & 1, pf);     // into the buffer freed at this kt's sync
            if (kt == 3) __syncthreads();        // A(next tile chunk0) visible for next iter
        }

        // ---- Epilogue: bias + relu; stores overlap next tile's first MMAs ----
        #pragma unroll
        for (int mt = 0; mt < 2; ++mt) {
            int r0 = m_base + warp_m * 32 + mt * 16 + gid;
            float* o0 = out + (size_t)r0 * N;
            float* o1 = out + (size_t)(r0 + 8) * N;
            #pragma unroll
            for (int nt = 0; nt < 8; ++nt) {
                int c = warp_n * 64 + nt * 8 + 2 * tg;
                float b0 = sbias[c], b1 = sbias[c + 1];
                float2 v0, v1;
                v0.x = fmaxf(acc[mt][nt][0] + b0, 0.0f);
                v0.y = fmaxf(acc[mt][nt][1] + b1, 0.0f);
                v1.x = fmaxf(acc[mt][nt][2] + b0, 0.0f);
                v1.y = fmaxf(acc[mt][nt][3] + b1, 0.0f);
                *reinterpret_cast<float2*>(o0 + c) = v0;
                *reinterpret_cast<float2*>(o1 + c) = v1;
                #pragma unroll
                for (int j = 0; j < 4; ++j)
                    acc[mt][nt][j] = 0.0f;
            }
        }
    }
}

extern "C" void kernel_launch(void* const* d_in, const int* in_sizes, int n_in,
                              void* d_out, int out_size) {
    const float* x = (const float*)d_in[0];
    const float* W = (const float*)d_in[1];
    const float* b = (const float*)d_in[2];
    float* out = (float*)d_out;

    convert_w_kernel<<<64, 256>>>(W);

    cudaFuncSetAttribute(gemm_f16_kernel,
                         cudaFuncAttributeMaxDynamicSharedMemorySize, SMEM_TOTAL);
    gemm_f16_kernel<<<NCTA, 512, SMEM_TOTAL>>>(x, b, out);
}

// round 12
// speedup vs baseline: 1.2338x; 1.2338x over previous
#include <cuda_runtime.h>
#include <cuda_fp16.h>
#include <cstdint>
#include <cstddef>

// out = relu(x[131072,256] @ W[256,256]^T + b[256]), fp32 in/out.
// Persistent fat-tile fp16 GEMM: 148 CTAs x 256 thr (8 warps), warp tile
// 64x64 (acc=128 fp32 regs, ~225 regs total, 1 CTA/SM), CTA tile 128x256.
// ALL of W fp16 resident in smem (160KB, loaded once). A: 4-stage smem ring,
// LDG prefetch distance 3 (latency fully hidden). Per kt: 16 batched
// ldmatrix.x4 then 64 MMAs. 1.0 L1-wavefront/MMA.

#define DEVI __device__ __forceinline__

static constexpr int M_TOTAL = 131072;
static constexpr int N = 256;
static constexpr int K = 256;
static constexpr int BM = 128;                  // M rows per tile
static constexpr int KC = 32;                   // K per chunk
static constexpr int NCHUNK = K / KC;           // 8
static constexpr int NCTA = 148;
static constexpr int STRB = 80;                 // row stride bytes (32h+8h pad)
static constexpr int A_STAGE = BM * STRB;       // 10240
static constexpr int B_STAGE = N * STRB;        // 20480
static constexpr int A_BASE = 1024;             // [0,1024) bias
static constexpr int B_BASE = A_BASE + 4 * A_STAGE;        // 41984
static constexpr int SMEM_TOTAL = B_BASE + NCHUNK * B_STAGE;  // 205824

__device__ __half g_wh[N * K];

DEVI uint32_t smem_u32(const void* p) {
    uint32_t a;
    asm("{ .reg .u64 t; cvta.to.shared.u64 t, %1; cvt.u32.u64 %0, t; }"
        : "=r"(a) : "l"(p));
    return a;
}

DEVI void cp16(uint32_t dst, const void* src) {
    asm volatile("cp.async.cg.shared.global [%0], [%1], 16;"
                 :: "r"(dst), "l"(__cvta_generic_to_global(src)) : "memory");
}

DEVI uint32_t pack_h2(float lo, float hi) {
    uint32_t r;
    asm("cvt.rn.f16x2.f32 %0, %1, %2;" : "=r"(r) : "f"(hi), "f"(lo));
    return r;
}

DEVI void ldm_x4(uint32_t* r, uint32_t addr) {
    asm volatile("ldmatrix.sync.aligned.m8n8.x4.shared.b16 {%0,%1,%2,%3}, [%4];"
                 : "=r"(r[0]), "=r"(r[1]), "=r"(r[2]), "=r"(r[3]) : "r"(addr));
}

DEVI void mma_f16(float* c, const uint32_t* a, const uint32_t* b) {
    asm volatile(
        "mma.sync.aligned.m16n8k16.row.col.f32.f16.f16.f32 "
        "{%0,%1,%2,%3}, {%4,%5,%6,%7}, {%8,%9}, {%0,%1,%2,%3};"
        : "+f"(c[0]), "+f"(c[1]), "+f"(c[2]), "+f"(c[3])
        : "r"(a[0]), "r"(a[1]), "r"(a[2]), "r"(a[3]), "r"(b[0]), "r"(b[1]));
}

__global__ void convert_w_kernel(const float* __restrict__ W) {
    int idx4 = (blockIdx.x * 256 + threadIdx.x) * 4;
    float4 v = *reinterpret_cast<const float4*>(W + idx4);
    uint2 h;
    h.x = pack_h2(v.x, v.y);
    h.y = pack_h2(v.z, v.w);
    *reinterpret_cast<uint2*>(g_wh + idx4) = h;
}

__global__ void __launch_bounds__(256, 1)
gemm_f16_kernel(const float* __restrict__ x,
                const float* __restrict__ bias,
                float* __restrict__ out) {
    extern __shared__ char smem[];
    float* sbias = reinterpret_cast<float*>(smem);
    const uint32_t sbase = smem_u32(smem);
    const int tid  = threadIdx.x;
    const int lane = tid & 31;
    const int wid  = tid >> 5;
    const int warp_m = wid >> 2;       // 0..1 (64 M rows each)
    const int warp_n = wid & 3;        // 0..3 (64 N cols each)
    const int gid = lane >> 2;
    const int tg  = lane & 3;

    sbias[tid] = bias[tid];

    // ldmatrix lane byte offsets (R7-validated mappings, scaled)
    const uint32_t aOff = (uint32_t)((warp_m * 64 + (lane & 15)) * STRB
                                     + (lane >> 4) * 16);
    const uint32_t bOff = (uint32_t)((warp_n * 64 + (lane & 7) + ((lane >> 4) << 3)) * STRB
                                     + ((lane >> 3) & 1) * 16);

    float acc[4][8][4];                // 128 fp32
    #pragma unroll
    for (int mt = 0; mt < 4; ++mt)
        #pragma unroll
        for (int nt = 0; nt < 8; ++nt)
            #pragma unroll
            for (int j = 0; j < 4; ++j)
                acc[mt][nt][j] = 0.0f;

    // A loader: 128 rows x 8 granules (16B src / 8B dst), 4 per thread
    const int ar = tid >> 3;           // row 0..31 (+32 per i)... g>>3 below
    const int ac = tid & 7;
    (void)ar; (void)ac;

    auto ldg_A = [&](int m_base, int kt, float4* pf) {
        const float* srcA = x + (size_t)m_base * K + kt * KC;
        #pragma unroll
        for (int i = 0; i < 4; ++i) {
            int g = tid + i * 256;
            int r = g >> 3, c = g & 7;
            pf[i] = *reinterpret_cast<const float4*>(srcA + (size_t)r * K + c * 4);
        }
    };
    auto sts_A = [&](int st, const float4* pf) {
        char* dA = smem + A_BASE + st * A_STAGE;
        #pragma unroll
        for (int i = 0; i < 4; ++i) {
            int g = tid + i * 256;
            int r = g >> 3, c = g & 7;
            uint2 h;
            h.x = pack_h2(pf[i].x, pf[i].y);
            h.y = pack_h2(pf[i].z, pf[i].w);
            *reinterpret_cast<uint2*>(dA + r * STRB + c * 8) = h;
        }
    };

    // ---- One-time prologue: all of W -> smem; A chunks 0..2 staged ----
    {
        #pragma unroll
        for (int i = 0; i < 32; ++i) {         // 8192 granules of B
            int g = tid + i * 256;
            int ck = g >> 10;
            int r  = (g >> 2) & 255;
            int c  = g & 3;
            cp16(sbase + B_BASE + ck * B_STAGE + r * STRB + c * 16,
                 g_wh + (size_t)r * K + ck * KC + c * 8);
        }
        asm volatile("cp.async.commit_group;" ::: "memory");

        const int m0 = blockIdx.x * BM;
        float4 pf[4];
        ldg_A(m0, 0, pf); sts_A(0, pf);
        ldg_A(m0, 1, pf); sts_A(1, pf);
        ldg_A(m0, 2, pf); sts_A(2, pf);
        asm volatile("cp.async.wait_group 0;" ::: "memory");
    }

    const int m_stride = NCTA * BM;

    // ---- Persistent tile loop ----
    #pragma unroll 1
    for (int m_base = blockIdx.x * BM; m_base < M_TOTAL; m_base += m_stride) {
        #pragma unroll 1
        for (int kt = 0; kt < NCHUNK; ++kt) {
            __syncthreads();   // A(kt) visible; stage (kt+3)&3 free to write

            // prefetch chunk kt+3 (possibly next tile's chunk kt-5)
            int fk = kt + 3;
            int fm = m_base;
            if (fk >= NCHUNK) { fk -= NCHUNK; fm += m_stride; }
            const bool has = (fm < M_TOTAL);
            float4 pf[4];
            if (has) ldg_A(fm, fk, pf);        // latency rides over 64 MMAs

            const uint32_t aB = sbase + A_BASE + (kt & 3) * A_STAGE + aOff;
            const uint32_t bB = sbase + B_BASE + kt * B_STAGE + bOff;

            // batch all fragments for both k16 steps (max LDSM MLP)
            uint32_t a[2][4][4], b[2][4][4];
            #pragma unroll
            for (int ks = 0; ks < 2; ++ks) {
                #pragma unroll
                for (int mt = 0; mt < 4; ++mt)
                    ldm_x4(a[ks][mt], aB + mt * (16 * STRB) + ks * 32);
                #pragma unroll
                for (int j = 0; j < 4; ++j)
                    ldm_x4(b[ks][j], bB + j * (16 * STRB) + ks * 32);
            }
            #pragma unroll
            for (int ks = 0; ks < 2; ++ks)
                #pragma unroll
                for (int mt = 0; mt < 4; ++mt)
                    #pragma unroll
                    for (int nt = 0; nt < 8; ++nt)
                        mma_f16(acc[mt][nt], a[ks][mt], &b[ks][nt >> 1][(nt & 1) * 2]);

            if (has) sts_A((kt + 3) & 3, pf);  // LDG data landed during MMAs
        }

        // ---- Epilogue: bias + relu; overlaps next tile's staged pipeline ----
        #pragma unroll
        for (int mt = 0; mt < 4; ++mt) {
            int r0 = m_base + warp_m * 64 + mt * 16 + gid;
            float* o0 = out + (size_t)r0 * N;
            float* o1 = out + (size_t)(r0 + 8) * N;
            #pragma unroll
            for (int nt = 0; nt < 8; ++nt) {
                int c = warp_n * 64 + nt * 8 + 2 * tg;
                float b0 = sbias[c], b1 = sbias[c + 1];
                float2 v0, v1;
                v0.x = fmaxf(acc[mt][nt][0] + b0, 0.0f);
                v0.y = fmaxf(acc[mt][nt][1] + b1, 0.0f);
                v1.x = fmaxf(acc[mt][nt][2] + b0, 0.0f);
                v1.y = fmaxf(acc[mt][nt][3] + b1, 0.0f);
                *reinterpret_cast<float2*>(o0 + c) = v0;
                *reinterpret_cast<float2*>(o1 + c) = v1;
                #pragma unroll
                for (int j = 0; j < 4; ++j)
                    acc[mt][nt][j] = 0.0f;
            }
        }
    }
}

extern "C" void kernel_launch(void* const* d_in, const int* in_sizes, int n_in,
                              void* d_out, int out_size) {
    const float* x = (const float*)d_in[0];
    const float* W = (const float*)d_in[1];
    const float* b = (const float*)d_in[2];
    float* out = (float*)d_out;

    convert_w_kernel<<<64, 256>>>(W);

    cudaFuncSetAttribute(gemm_f16_kernel,
                         cudaFuncAttributeMaxDynamicSharedMemorySize, SMEM_TOTAL);
    gemm_f16_kernel<<<NCTA, 256, SMEM_TOTAL>>>(x, b, out);
}

// round 14
// speedup vs baseline: 1.3609x; 1.1030x over previous
#include <cuda_runtime.h>
#include <cuda_fp16.h>
#include <cstdint>
#include <cstddef>

// out = relu(x[131072,256] @ W[256,256]^T + b[256]), fp32 in/out.
// Persistent fat-tile fp16 GEMM: 148 CTAs x 256 thr (8 warps), warp tile
// 64x64, CTA tile 128x256. W fp16 fully smem-resident (148KB, loaded once).
// KC=64 -> only 4 barriers per tile, 128 MMAs per barrier. A: 3-stage smem
// ring, LDG prefetch distance 2 (~2 MMA blocks of slack).

#define DEVI __device__ __forceinline__

static constexpr int M_TOTAL = 131072;
static constexpr int N = 256;
static constexpr int K = 256;
static constexpr int BM = 128;                  // M rows per tile
static constexpr int KC = 64;                   // K per chunk
static constexpr int NCHUNK = K / KC;           // 4
static constexpr int NCTA = 148;
static constexpr int STRB = 144;                // row stride bytes (64h+8h pad)
static constexpr int A_STAGE = BM * STRB;       // 18432
static constexpr int B_STAGE = N * STRB;        // 36864
static constexpr int A_BASE = 1024;             // [0,1024) bias
static constexpr int B_BASE = A_BASE + 3 * A_STAGE;           // 56320
static constexpr int SMEM_TOTAL = B_BASE + NCHUNK * B_STAGE;  // 203776

__device__ __half g_wh[N * K];

DEVI uint32_t smem_u32(const void* p) {
    uint32_t a;
    asm("{ .reg .u64 t; cvta.to.shared.u64 t, %1; cvt.u32.u64 %0, t; }"
        : "=r"(a) : "l"(p));
    return a;
}

DEVI void cp16(uint32_t dst, const void* src) {
    asm volatile("cp.async.cg.shared.global [%0], [%1], 16;"
                 :: "r"(dst), "l"(__cvta_generic_to_global(src)) : "memory");
}

DEVI uint32_t pack_h2(float lo, float hi) {
    uint32_t r;
    asm("cvt.rn.f16x2.f32 %0, %1, %2;" : "=r"(r) : "f"(hi), "f"(lo));
    return r;
}

DEVI void ldm_x4(uint32_t* r, uint32_t addr) {
    asm volatile("ldmatrix.sync.aligned.m8n8.x4.shared.b16 {%0,%1,%2,%3}, [%4];"
                 : "=r"(r[0]), "=r"(r[1]), "=r"(r[2]), "=r"(r[3]) : "r"(addr));
}

DEVI void mma_f16(float* c, const uint32_t* a, const uint32_t* b) {
    asm volatile(
        "mma.sync.aligned.m16n8k16.row.col.f32.f16.f16.f32 "
        "{%0,%1,%2,%3}, {%4,%5,%6,%7}, {%8,%9}, {%0,%1,%2,%3};"
        : "+f"(c[0]), "+f"(c[1]), "+f"(c[2]), "+f"(c[3])
        : "r"(a[0]), "r"(a[1]), "r"(a[2]), "r"(a[3]), "r"(b[0]), "r"(b[1]));
}

__global__ void convert_w_kernel(const float* __restrict__ W) {
    int idx4 = (blockIdx.x * 256 + threadIdx.x) * 4;
    float4 v = *reinterpret_cast<const float4*>(W + idx4);
    uint2 h;
    h.x = pack_h2(v.x, v.y);
    h.y = pack_h2(v.z, v.w);
    *reinterpret_cast<uint2*>(g_wh + idx4) = h;
}

__global__ void __launch_bounds__(256, 1)
gemm_f16_kernel(const float* __restrict__ x,
                const float* __restrict__ bias,
                float* __restrict__ out) {
    extern __shared__ char smem[];
    float* sbias = reinterpret_cast<float*>(smem);
    const uint32_t sbase = smem_u32(smem);
    const int tid  = threadIdx.x;
    const int lane = tid & 31;
    const int wid  = tid >> 5;
    const int warp_m = wid >> 2;       // 0..1 (64 M rows each)
    const int warp_n = wid & 3;        // 0..3 (64 N cols each)
    const int gid = lane >> 2;
    const int tg  = lane & 3;

    sbias[tid] = bias[tid];

    const uint32_t aOff = (uint32_t)((warp_m * 64 + (lane & 15)) * STRB
                                     + (lane >> 4) * 16);
    const uint32_t bOff = (uint32_t)((warp_n * 64 + (lane & 7) + ((lane >> 4) << 3)) * STRB
                                     + ((lane >> 3) & 1) * 16);

    float acc[4][8][4];                // 128 fp32
    #pragma unroll
    for (int mt = 0; mt < 4; ++mt)
        #pragma unroll
        for (int nt = 0; nt < 8; ++nt)
            #pragma unroll
            for (int j = 0; j < 4; ++j)
                acc[mt][nt][j] = 0.0f;

    // A loader (KC=64): 128 rows x 16 granules (16B src / 8B dst), 8/thread
    auto ldg_A = [&](int m_base, int kt, float4* pf) {
        const float* srcA = x + (size_t)m_base * K + kt * KC;
        #pragma unroll
        for (int i = 0; i < 8; ++i) {
            int g = tid + i * 256;
            int r = g >> 4, c = g & 15;
            pf[i] = *reinterpret_cast<const float4*>(srcA + (size_t)r * K + c * 4);
        }
    };
    auto sts_A = [&](int st, const float4* pf) {
        char* dA = smem + A_BASE + st * A_STAGE;
        #pragma unroll
        for (int i = 0; i < 8; ++i) {
            int g = tid + i * 256;
            int r = g >> 4, c = g & 15;
            uint2 h;
            h.x = pack_h2(pf[i].x, pf[i].y);
            h.y = pack_h2(pf[i].z, pf[i].w);
            *reinterpret_cast<uint2*>(dA + r * STRB + c * 8) = h;
        }
    };

    // ---- One-time prologue: all of W -> smem; A chunks 0,1 staged ----
    {
        // B: 4 chunks x 256 rows x 8 16B-granules = 8192 granules, 32/thread
        #pragma unroll
        for (int i = 0; i < 32; ++i) {
            int g = tid + i * 256;
            int ck = g >> 11;                  // 2048 granules per chunk
            int r  = (g >> 3) & 255;
            int c  = g & 7;
            cp16(sbase + B_BASE + ck * B_STAGE + r * STRB + c * 16,
                 g_wh + (size_t)r * K + ck * KC + c * 8);
        }
        asm volatile("cp.async.commit_group;" ::: "memory");

        const int m0 = blockIdx.x * BM;
        float4 pf[8];
        ldg_A(m0, 0, pf); sts_A(0, pf);
        ldg_A(m0, 1, pf); sts_A(1, pf);
        asm volatile("cp.async.wait_group 0;" ::: "memory");
    }

    const int m_stride = NCTA * BM;

    // ---- Persistent tile loop; global chunk counter drives the 3-stage ring ----
    int cglob = 0;   // global chunk index of current kt (stage = cglob % 3)
    #pragma unroll 1
    for (int m_base = blockIdx.x * BM; m_base < M_TOTAL; m_base += m_stride) {
        #pragma unroll 1
        for (int kt = 0; kt < NCHUNK; ++kt, ++cglob) {
            __syncthreads();   // A(cglob) visible; stage (cglob+2)%3 free

            // prefetch chunk cglob+2 (possibly next tile's chunk)
            int fk = kt + 2;
            int fm = m_base;
            if (fk >= NCHUNK) { fk -= NCHUNK; fm += m_stride; }
            const bool has = (fm < M_TOTAL);
            float4 pf[8];
            if (has) ldg_A(fm, fk, pf);        // rides over 128 MMAs

            int st = cglob % 3;
            const uint32_t aB = sbase + A_BASE + st * A_STAGE + aOff;
            const uint32_t bB = sbase + B_BASE + kt * B_STAGE + bOff;

            #pragma unroll
            for (int ks = 0; ks < 4; ++ks) {   // 4 k16 steps per chunk
                uint32_t a[4][4], b[4][4];
                #pragma unroll
                for (int mt = 0; mt < 4; ++mt)
                    ldm_x4(a[mt], aB + mt * (16 * STRB) + ks * 32);
                #pragma unroll
                for (int j = 0; j < 4; ++j)
                    ldm_x4(b[j], bB + j * (16 * STRB) + ks * 32);
                #pragma unroll
                for (int mt = 0; mt < 4; ++mt)
                    #pragma unroll
                    for (int nt = 0; nt < 8; ++nt)
                        mma_f16(acc[mt][nt], a[mt], &b[nt >> 1][(nt & 1) * 2]);
            }

            int fst = (cglob + 2) % 3;
            if (has) sts_A(fst, pf);           // LDG data landed during MMAs
        }

        // ---- Epilogue: bias + relu; next-tile A already staged/in-flight ----
        #pragma unroll
        for (int mt = 0; mt < 4; ++mt) {
            int r0 = m_base + warp_m * 64 + mt * 16 + gid;
            float* o0 = out + (size_t)r0 * N;
            float* o1 = out + (size_t)(r0 + 8) * N;
            #pragma unroll
            for (int nt = 0; nt < 8; ++nt) {
                int c = warp_n * 64 + nt * 8 + 2 * tg;
                float b0 = sbias[c], b1 = sbias[c + 1];
                float2 v0, v1;
                v0.x = fmaxf(acc[mt][nt][0] + b0, 0.0f);
                v0.y = fmaxf(acc[mt][nt][1] + b1, 0.0f);
                v1.x = fmaxf(acc[mt][nt][2] + b0, 0.0f);
                v1.y = fmaxf(acc[mt][nt][3] + b1, 0.0f);
                *reinterpret_cast<float2*>(o0 + c) = v0;
                *reinterpret_cast<float2*>(o1 + c) = v1;
                #pragma unroll
                for (int j = 0; j < 4; ++j)
                    acc[mt][nt][j] = 0.0f;
            }
        }
    }
}

extern "C" void kernel_launch(void* const* d_in, const int* in_sizes, int n_in,
                              void* d_out, int out_size) {
    const float* x = (const float*)d_in[0];
    const float* W = (const float*)d_in[1];
    const float* b = (const float*)d_in[2];
    float* out = (float*)d_out;

    convert_w_kernel<<<64, 256>>>(W);

    cudaFuncSetAttribute(gemm_f16_kernel,
                         cudaFuncAttributeMaxDynamicSharedMemorySize, SMEM_TOTAL);
    gemm_f16_kernel<<<NCTA, 256, SMEM_TOTAL>>>(x, b, out);
}